// round 9
// baseline (speedup 1.0000x reference)
#include <cuda_runtime.h>
#include <math.h>

#define B 64
#define S 256
#define INSZ 128
#define H 512
#define G4 2048          // 4*H
#define NTOK (B*S)       // 16384
#define NCTA 128

// ---------------- scratch (device globals; no allocation allowed) ----------------
// xg is GATE-MAJOR: g_xg[t][gate(2048)][b(64)] ; token order is tok = t*64 + b
__device__ float g_xg[(size_t)NTOK * G4];        // 128 MB
__device__ float g_hseq[(size_t)NTOK * H];       // 32 MB: layer-0 hidden, row = tok = t*64+b
__device__ float g_h[2][H * B];                  // double-buffered hidden state, layout [k][b]
__device__ float g_wdup[2][(size_t)G4 * H * 2];  // 16 MB: W_hh duplicated {w,w}, blocked per CTA

// grid barrier state (persists across replays; relative-gen logic is replay-safe)
__device__ unsigned g_bar_cnt = 0;
__device__ volatile unsigned g_bar_gen = 0;

typedef unsigned long long ull;

__device__ __forceinline__ ull pack2(float lo, float hi) {
    ull r; asm("mov.b64 %0, {%1, %2};" : "=l"(r) : "f"(lo), "f"(hi)); return r;
}
__device__ __forceinline__ void unpack2(ull v, float& lo, float& hi) {
    asm("mov.b64 {%0, %1}, %2;" : "=f"(lo), "=f"(hi) : "l"(v));
}
__device__ __forceinline__ void fma2(ull& d, ull a, ull b) {
    asm("fma.rn.f32x2 %0, %1, %2, %0;" : "+l"(d) : "l"(a), "l"(b));
}
__device__ __forceinline__ float ldcs32(const float* p) {
    float v; asm volatile("ld.global.cs.b32 %0, [%1];" : "=f"(v) : "l"(p)); return v;
}
__device__ __forceinline__ float sigm(float x) {
    return __fdividef(1.0f, 1.0f + __expf(-x));
}
__device__ __forceinline__ float tanh_fast(float x) {
    // 1 - 2/(e^{2x}+1); saturates to +/-1 for large |x| (e -> inf or 0)
    float e = __expf(2.0f * x);
    return 1.0f - __fdividef(2.0f, e + 1.0f);
}

// ---------------- prep: duplicate W_hh into CTA-blocked {w,w} layout ----------------
__global__ void prep_wdup_kernel(const float* __restrict__ W0, const float* __restrict__ W1) {
    int idx = blockIdx.x * blockDim.x + threadIdx.x;   // 2 * 2^20 total
    int l = idx >> 20;
    int r = idx & ((1 << 20) - 1);
    int j = r >> 11;
    int g = (r >> 9) & 3;
    int k = r & 511;
    const float* W = l ? W1 : W0;
    float v = W[(g * 512 + j) * 512 + k];
    float* dst = &g_wdup[l][(((size_t)(j * 4 + g)) * 512 + k) * 2];
    dst[0] = v; dst[1] = v;
}

// ---------------- big GEMM: xgT[t][n][b] = A[tok][:] . W[n][:] + b1[n] + b2[n] ----------------
// token order tok = t*64 + b. layer0: A row tok -> x[(b*256+t)*128]. layer1: A = g_hseq[tok*512].
#define BM 128
#define BN 128
#define BKT 16
#define LDT 132

__global__ __launch_bounds__(256) void gemm_bias_kernel(
    const float* __restrict__ x_in, const float* __restrict__ W,
    const float* __restrict__ b1, const float* __restrict__ b2,
    int K, int layer)
{
    __shared__ __align__(16) float As[BKT][LDT];
    __shared__ __align__(16) float Bs[BKT][LDT];
    __shared__ __align__(16) float Cs[BM][33];
    int tid = threadIdx.x;
    int m0 = blockIdx.y * BM, n0 = blockIdx.x * BN;
    int tx = tid & 15, ty = tid >> 4;

    ull acc[8][4];
    #pragma unroll
    for (int i = 0; i < 8; i++)
        #pragma unroll
        for (int j = 0; j < 4; j++) acc[i][j] = 0ull;

    for (int k0 = 0; k0 < K; k0 += BKT) {
        #pragma unroll
        for (int r = 0; r < 2; r++) {
            int f = tid + r * 256;
            int m = f >> 2, kq = (f & 3) * 4;
            int tok = m0 + m;
            size_t arow = layer ? (size_t)tok * 512
                                : ((size_t)(tok & 63) * 256 + (tok >> 6)) * 128;
            const float* Ap = layer ? g_hseq : x_in;
            float4 va = __ldg((const float4*)&Ap[arow + k0 + kq]);
            As[kq + 0][m] = va.x; As[kq + 1][m] = va.y;
            As[kq + 2][m] = va.z; As[kq + 3][m] = va.w;
            float4 vb = __ldg((const float4*)&W[(size_t)(n0 + m) * K + k0 + kq]);
            Bs[kq + 0][m] = vb.x; Bs[kq + 1][m] = vb.y;
            Bs[kq + 2][m] = vb.z; Bs[kq + 3][m] = vb.w;
        }
        __syncthreads();
        #pragma unroll
        for (int k = 0; k < BKT; k++) {
            float4 a0 = *(const float4*)&As[k][ty * 8];
            float4 a1 = *(const float4*)&As[k][ty * 8 + 4];
            ulonglong2 bb0 = *(const ulonglong2*)&Bs[k][tx * 8];
            ulonglong2 bb1 = *(const ulonglong2*)&Bs[k][tx * 8 + 4];
            ull bb[4] = {bb0.x, bb0.y, bb1.x, bb1.y};
            float av[8] = {a0.x, a0.y, a0.z, a0.w, a1.x, a1.y, a1.z, a1.w};
            #pragma unroll
            for (int i = 0; i < 8; i++) {
                ull ad = pack2(av[i], av[i]);
                #pragma unroll
                for (int j = 0; j < 4; j++) fma2(acc[i][j], ad, bb[j]);
            }
        }
        __syncthreads();
    }

    float bs[8];
    #pragma unroll
    for (int j = 0; j < 8; j++) {
        int n = n0 + tx * 8 + j;
        bs[j] = __ldg(&b1[n]) + __ldg(&b2[n]);
    }

    // transposed epilogue: stage 32-col chunks in SMEM, write g_xg[t][n][b] coalesced
    for (int c = 0; c < 4; c++) {
        if ((tx >> 2) == c) {
            #pragma unroll
            for (int i = 0; i < 8; i++) {
                float o[8];
                #pragma unroll
                for (int j = 0; j < 4; j++) {
                    float lo, hi; unpack2(acc[i][j], lo, hi);
                    o[j * 2] = lo + bs[j * 2]; o[j * 2 + 1] = hi + bs[j * 2 + 1];
                }
                #pragma unroll
                for (int jj = 0; jj < 8; jj++)
                    Cs[ty * 8 + i][(tx & 3) * 8 + jj] = o[jj];
            }
        }
        __syncthreads();
        // copy out: 32 n-cols x 128 tokens; token = m0+m, t = token>>6, b = token&63
        int nn = tid >> 3;
        int q0 = tid & 7;
        #pragma unroll
        for (int it = 0; it < 4; it++) {
            int m = (q0 + it * 8) * 4;
            float4 f4 = make_float4(Cs[m][nn], Cs[m + 1][nn], Cs[m + 2][nn], Cs[m + 3][nn]);
            int token = m0 + m;
            int t = token >> 6, b = token & 63;
            int n = n0 + c * 32 + nn;
            *(float4*)&g_xg[((size_t)t * G4 + n) * 64 + b] = f4;
        }
        __syncthreads();
    }
}

// ---------------- persistent LSTM recurrence (all 256 steps in one launch) ----------------
// 128 CTAs x 512 threads. CTA owns 4 hidden units (64KB dup W slice in SMEM, loaded once).
// Matvec: warp w -> up = w&1 (unit pair), kq = w>>1 (k-eighth of 64 k); lane = batch pair.
// Partials go to ps[kq][u][g][b] (conflict-free STS.64).
// Epilogue: 256 threads, thread = (u = tid>>6, b = tid&63); conflict-free LDS.32 reduction,
// coalesced xg loads and h stores; c state lives in these threads' registers.
// h read through L1 (default cached): coherent because every CTA's barrier executes
// __threadfence() (gpu scope -> CCTL.IVALL) between h production and consumption.
__global__ __launch_bounds__(512) void lstm_persist_kernel(int layer)
{
    extern __shared__ __align__(16) float Wd[];     // 64KB: [u][g][k][2]
    __shared__ __align__(16) float ps[8][4][4][64]; // 32KB: partials [kq][u][g][b]
    __shared__ __align__(16) float hs[64][5];       // padded transpose stage for hseq

    int tid = threadIdx.x;
    int lane = tid & 31;
    int w = tid >> 5;
    int up = w & 1;
    int kq = w >> 1;           // 0..7, 64 k each
    int b0 = lane * 2;

    // epilogue identity (threads 0..255)
    int eu = tid >> 6;         // unit 0..3 (valid when tid < 256)
    int eb = tid & 63;         // batch
    int ej = blockIdx.x * 4 + eu;

    // stage W slice once
    {
        const float4* src = (const float4*)&g_wdup[layer][(size_t)blockIdx.x * 16384];
        float4* dst = (float4*)Wd;
        #pragma unroll
        for (int i = 0; i < 8; i++) dst[tid + i * 512] = __ldg(&src[tid + i * 512]);
    }
    __syncthreads();

    // W addr for (u, g, kq*64 + kk): u*4096 + g*1024 + kq*128 + kk*2
    const float* Wu0 = Wd + (2 * up) * 4096 + kq * 128;
    const float* Wu1 = Wu0 + 4096;
    float cc = 0.0f;   // cell state for epilogue thread (eu, eb)

    for (int t = 0; t < S; t++) {
        // ---- matvec over this warp's 64-k slice ----
        ull acc[2][4] = {{0,0,0,0},{0,0,0,0}};
        if (t > 0) {
            const ull* hp = (const ull*)(g_h[t & 1] + kq * 64 * 64);
            #pragma unroll 4
            for (int kk = 0; kk < 64; kk += 2) {
                ull h0 = hp[kk * 32 + lane];          // {h[k][b0], h[k][b0+1]}
                ull h1 = hp[(kk + 1) * 32 + lane];
                #pragma unroll
                for (int g = 0; g < 4; g++) {
                    ulonglong2 w0 = *(const ulonglong2*)&Wu0[g * 1024 + kk * 2];
                    fma2(acc[0][g], h0, w0.x);
                    fma2(acc[0][g], h1, w0.y);
                    ulonglong2 w1 = *(const ulonglong2*)&Wu1[g * 1024 + kk * 2];
                    fma2(acc[1][g], h0, w1.x);
                    fma2(acc[1][g], h1, w1.y);
                }
            }
        }

        // write partials (lane-contiguous -> conflict-free STS.64)
        #pragma unroll
        for (int un = 0; un < 2; un++)
            #pragma unroll
            for (int g = 0; g < 4; g++)
                *(ull*)&ps[kq][up * 2 + un][g][b0] = acc[un][g];

        // issue xg loads BEFORE the sync so DRAM latency overlaps the barrier wait
        float xv[4];
        if (tid < 256) {
            #pragma unroll
            for (int g = 0; g < 4; g++)
                xv[g] = ldcs32(&g_xg[((size_t)t * G4 + g * 512 + ej) * 64 + eb]);
        }
        __syncthreads();

        // ---- epilogue: 256 threads, one per (unit, batch) ----
        if (tid < 256) {
            float s[4];
            #pragma unroll
            for (int g = 0; g < 4; g++) {
                float a = xv[g];
                #pragma unroll
                for (int q = 0; q < 8; q++) a += ps[q][eu][g][eb];  // conflict-free LDS.32
                s[g] = a;
            }
            float i_ = sigm(s[0]);
            float f_ = sigm(s[1]);
            float gg = tanh_fast(s[2]);
            float o_ = sigm(s[3]);
            cc = f_ * cc + i_ * gg;
            float hh = o_ * tanh_fast(cc);

            g_h[(t + 1) & 1][ej * 64 + eb] = hh;    // tid-linear -> coalesced
            if (layer == 0) hs[eb][eu] = hh;        // 5-padded -> conflict-free
        }

        if (layer == 0) {
            __syncthreads();
            if (tid < 64) {
                float4 v = make_float4(hs[tid][0], hs[tid][1], hs[tid][2], hs[tid][3]);
                *(float4*)&g_hseq[((size_t)t * 64 + tid) * 512 + blockIdx.x * 4] = v;
            }
        }

        // ---- grid barrier (skip after last step) ----
        if (t != S - 1) {
            __syncthreads();
            if (tid == 0) {
                unsigned gen = g_bar_gen;
                __threadfence();   // drain h stores to L2
                if (atomicAdd(&g_bar_cnt, 1u) == NCTA - 1) {
                    g_bar_cnt = 0;
                    __threadfence();
                    g_bar_gen = gen + 1;
                } else {
                    while (g_bar_gen == gen) { }
                }
                __threadfence();   // gpu-scope fence -> CCTL.IVALL: L1 coherence for h
            }
            __syncthreads();
        }
    }
}

// ---------------- final FC: out[b][o] = h_last[:,b] . W_fc[o][:] + b_fc[o] ----------------
__global__ void fc_kernel(const float* __restrict__ Wfc, const float* __restrict__ bfc,
                          float* __restrict__ out)
{
    __shared__ float hcol[H];
    int b = blockIdx.x;
    int o = threadIdx.x;   // 64 threads
    for (int k = o; k < H; k += 64) hcol[k] = g_h[0][k * 64 + b];
    __syncthreads();
    float acc = __ldg(&bfc[o]);
    #pragma unroll 8
    for (int k = 0; k < H; k++) acc += hcol[k] * __ldg(&Wfc[o * 512 + k]);
    out[b * 64 + o] = acc;
}

// ---------------- launch ----------------
extern "C" void kernel_launch(void* const* d_in, const int* in_sizes, int n_in,
                              void* d_out, int out_size)
{
    const float* x      = (const float*)d_in[0];
    const float* W_ih_0 = (const float*)d_in[1];
    const float* W_hh_0 = (const float*)d_in[2];
    const float* b_ih_0 = (const float*)d_in[3];
    const float* b_hh_0 = (const float*)d_in[4];
    const float* W_ih_1 = (const float*)d_in[5];
    const float* W_hh_1 = (const float*)d_in[6];
    const float* b_ih_1 = (const float*)d_in[7];
    const float* b_hh_1 = (const float*)d_in[8];
    const float* W_fc   = (const float*)d_in[9];
    const float* b_fc   = (const float*)d_in[10];
    float* out = (float*)d_out;

    cudaFuncSetAttribute(lstm_persist_kernel, cudaFuncAttributeMaxDynamicSharedMemorySize, 65536);

    prep_wdup_kernel<<<8192, 256>>>(W_hh_0, W_hh_1);

    // ---- layer 0 ----
    gemm_bias_kernel<<<dim3(16, 128), 256>>>(x, W_ih_0, b_ih_0, b_hh_0, INSZ, 0);
    lstm_persist_kernel<<<NCTA, 512, 65536>>>(0);

    // ---- layer 1 ----
    gemm_bias_kernel<<<dim3(16, 128), 256>>>(x, W_ih_1, b_ih_1, b_hh_1, H, 1);
    lstm_persist_kernel<<<NCTA, 512, 65536>>>(1);

    // ---- head ----
    fc_kernel<<<64, 64>>>(W_fc, b_fc, out);
}

// round 10
// speedup vs baseline: 1.0003x; 1.0003x over previous
#include <cuda_runtime.h>
#include <math.h>

#define B 64
#define S 256
#define INSZ 128
#define H 512
#define G4 2048          // 4*H
#define NTOK (B*S)       // 16384
#define NCTA 128

// ---------------- scratch (device globals; no allocation allowed) ----------------
// xg is GATE-MAJOR: g_xg[t][gate(2048)][b(64)] ; token order is tok = t*64 + b
__device__ float g_xg[(size_t)NTOK * G4];        // 128 MB
__device__ float g_hseq[(size_t)NTOK * H];       // 32 MB: layer-0 hidden, row = tok = t*64+b
__device__ float g_h[2][H * B];                  // double-buffered hidden state, layout [k][b]
__device__ float g_wdup[2][(size_t)G4 * H * 2];  // 16 MB: W_hh duplicated {w,w}, blocked per CTA

// grid barrier state (persists across replays; relative-gen logic is replay-safe)
__device__ unsigned g_bar_cnt = 0;
__device__ volatile unsigned g_bar_gen = 0;

typedef unsigned long long ull;

__device__ __forceinline__ ull pack2(float lo, float hi) {
    ull r; asm("mov.b64 %0, {%1, %2};" : "=l"(r) : "f"(lo), "f"(hi)); return r;
}
__device__ __forceinline__ void unpack2(ull v, float& lo, float& hi) {
    asm("mov.b64 {%0, %1}, %2;" : "=f"(lo), "=f"(hi) : "l"(v));
}
__device__ __forceinline__ void fma2(ull& d, ull a, ull b) {
    asm("fma.rn.f32x2 %0, %1, %2, %0;" : "+l"(d) : "l"(a), "l"(b));
}
__device__ __forceinline__ float ldcs32(const float* p) {
    float v; asm volatile("ld.global.cs.b32 %0, [%1];" : "=f"(v) : "l"(p)); return v;
}
__device__ __forceinline__ float sigm(float x) {
    return __fdividef(1.0f, 1.0f + __expf(-x));
}
__device__ __forceinline__ float tanh_fast(float x) {
    // 1 - 2/(e^{2x}+1); saturates to +/-1 for large |x| (e -> inf or 0)
    float e = __expf(2.0f * x);
    return 1.0f - __fdividef(2.0f, e + 1.0f);
}

// ---------------- prep: duplicate W_hh into CTA-blocked {w,w} layout ----------------
__global__ void prep_wdup_kernel(const float* __restrict__ W0, const float* __restrict__ W1) {
    int idx = blockIdx.x * blockDim.x + threadIdx.x;   // 2 * 2^20 total
    int l = idx >> 20;
    int r = idx & ((1 << 20) - 1);
    int j = r >> 11;
    int g = (r >> 9) & 3;
    int k = r & 511;
    const float* W = l ? W1 : W0;
    float v = W[(g * 512 + j) * 512 + k];
    float* dst = &g_wdup[l][(((size_t)(j * 4 + g)) * 512 + k) * 2];
    dst[0] = v; dst[1] = v;
}

// ---------------- big GEMM: xgT[t][n][b] = A[tok][:] . W[n][:] + b1[n] + b2[n] ----------------
// token order tok = t*64 + b. layer0: A row tok -> x[(b*256+t)*128]. layer1: A = g_hseq[tok*512].
#define BM 128
#define BN 128
#define BKT 16
#define LDT 132

__global__ __launch_bounds__(256) void gemm_bias_kernel(
    const float* __restrict__ x_in, const float* __restrict__ W,
    const float* __restrict__ b1, const float* __restrict__ b2,
    int K, int layer)
{
    __shared__ __align__(16) float As[BKT][LDT];
    __shared__ __align__(16) float Bs[BKT][LDT];
    __shared__ __align__(16) float Cs[BM][33];
    int tid = threadIdx.x;
    int m0 = blockIdx.y * BM, n0 = blockIdx.x * BN;
    int tx = tid & 15, ty = tid >> 4;

    ull acc[8][4];
    #pragma unroll
    for (int i = 0; i < 8; i++)
        #pragma unroll
        for (int j = 0; j < 4; j++) acc[i][j] = 0ull;

    for (int k0 = 0; k0 < K; k0 += BKT) {
        #pragma unroll
        for (int r = 0; r < 2; r++) {
            int f = tid + r * 256;
            int m = f >> 2, kq = (f & 3) * 4;
            int tok = m0 + m;
            size_t arow = layer ? (size_t)tok * 512
                                : ((size_t)(tok & 63) * 256 + (tok >> 6)) * 128;
            const float* Ap = layer ? g_hseq : x_in;
            float4 va = __ldg((const float4*)&Ap[arow + k0 + kq]);
            As[kq + 0][m] = va.x; As[kq + 1][m] = va.y;
            As[kq + 2][m] = va.z; As[kq + 3][m] = va.w;
            float4 vb = __ldg((const float4*)&W[(size_t)(n0 + m) * K + k0 + kq]);
            Bs[kq + 0][m] = vb.x; Bs[kq + 1][m] = vb.y;
            Bs[kq + 2][m] = vb.z; Bs[kq + 3][m] = vb.w;
        }
        __syncthreads();
        #pragma unroll
        for (int k = 0; k < BKT; k++) {
            float4 a0 = *(const float4*)&As[k][ty * 8];
            float4 a1 = *(const float4*)&As[k][ty * 8 + 4];
            ulonglong2 bb0 = *(const ulonglong2*)&Bs[k][tx * 8];
            ulonglong2 bb1 = *(const ulonglong2*)&Bs[k][tx * 8 + 4];
            ull bb[4] = {bb0.x, bb0.y, bb1.x, bb1.y};
            float av[8] = {a0.x, a0.y, a0.z, a0.w, a1.x, a1.y, a1.z, a1.w};
            #pragma unroll
            for (int i = 0; i < 8; i++) {
                ull ad = pack2(av[i], av[i]);
                #pragma unroll
                for (int j = 0; j < 4; j++) fma2(acc[i][j], ad, bb[j]);
            }
        }
        __syncthreads();
    }

    float bs[8];
    #pragma unroll
    for (int j = 0; j < 8; j++) {
        int n = n0 + tx * 8 + j;
        bs[j] = __ldg(&b1[n]) + __ldg(&b2[n]);
    }

    // transposed epilogue: stage 32-col chunks in SMEM, write g_xg[t][n][b] coalesced
    for (int c = 0; c < 4; c++) {
        if ((tx >> 2) == c) {
            #pragma unroll
            for (int i = 0; i < 8; i++) {
                float o[8];
                #pragma unroll
                for (int j = 0; j < 4; j++) {
                    float lo, hi; unpack2(acc[i][j], lo, hi);
                    o[j * 2] = lo + bs[j * 2]; o[j * 2 + 1] = hi + bs[j * 2 + 1];
                }
                #pragma unroll
                for (int jj = 0; jj < 8; jj++)
                    Cs[ty * 8 + i][(tx & 3) * 8 + jj] = o[jj];
            }
        }
        __syncthreads();
        // copy out: 32 n-cols x 128 tokens; token = m0+m, t = token>>6, b = token&63
        int nn = tid >> 3;
        int q0 = tid & 7;
        #pragma unroll
        for (int it = 0; it < 4; it++) {
            int m = (q0 + it * 8) * 4;
            float4 f4 = make_float4(Cs[m][nn], Cs[m + 1][nn], Cs[m + 2][nn], Cs[m + 3][nn]);
            int token = m0 + m;
            int t = token >> 6, b = token & 63;
            int n = n0 + c * 32 + nn;
            *(float4*)&g_xg[((size_t)t * G4 + n) * 64 + b] = f4;
        }
        __syncthreads();
    }
}

// ---------------- persistent LSTM recurrence (all 256 steps in one launch) ----------------
// 128 CTAs x 512 threads. CTA owns 4 hidden units (64KB dup W slice in SMEM, loaded once).
// Matvec: warp w -> up = w&1 (unit pair), kq = w>>1 (k-eighth of 64 k); lane = batch pair.
// Partials go to ps[kq][u][g][b] (conflict-free STS.64).
// Epilogue: 256 threads, thread = (u = tid>>6, b = tid&63); conflict-free LDS.32 reduction,
// coalesced xg loads and h stores; c state lives in these threads' registers.
// h read through L1 (default cached): coherent because every CTA's barrier executes
// __threadfence() (gpu scope -> CCTL.IVALL) between h production and consumption.
__global__ __launch_bounds__(512) void lstm_persist_kernel(int layer)
{
    extern __shared__ __align__(16) float Wd[];     // 64KB: [u][g][k][2]
    __shared__ __align__(16) float ps[8][4][4][64]; // 32KB: partials [kq][u][g][b]
    __shared__ __align__(16) float hs[64][5];       // padded transpose stage for hseq

    int tid = threadIdx.x;
    int lane = tid & 31;
    int w = tid >> 5;
    int up = w & 1;
    int kq = w >> 1;           // 0..7, 64 k each
    int b0 = lane * 2;

    // epilogue identity (threads 0..255)
    int eu = tid >> 6;         // unit 0..3 (valid when tid < 256)
    int eb = tid & 63;         // batch
    int ej = blockIdx.x * 4 + eu;

    // stage W slice once
    {
        const float4* src = (const float4*)&g_wdup[layer][(size_t)blockIdx.x * 16384];
        float4* dst = (float4*)Wd;
        #pragma unroll
        for (int i = 0; i < 8; i++) dst[tid + i * 512] = __ldg(&src[tid + i * 512]);
    }
    __syncthreads();

    // W addr for (u, g, kq*64 + kk): u*4096 + g*1024 + kq*128 + kk*2
    const float* Wu0 = Wd + (2 * up) * 4096 + kq * 128;
    const float* Wu1 = Wu0 + 4096;
    float cc = 0.0f;   // cell state for epilogue thread (eu, eb)

    for (int t = 0; t < S; t++) {
        // ---- matvec over this warp's 64-k slice ----
        ull acc[2][4] = {{0,0,0,0},{0,0,0,0}};
        if (t > 0) {
            const ull* hp = (const ull*)(g_h[t & 1] + kq * 64 * 64);
            #pragma unroll 4
            for (int kk = 0; kk < 64; kk += 2) {
                ull h0 = hp[kk * 32 + lane];          // {h[k][b0], h[k][b0+1]}
                ull h1 = hp[(kk + 1) * 32 + lane];
                #pragma unroll
                for (int g = 0; g < 4; g++) {
                    ulonglong2 w0 = *(const ulonglong2*)&Wu0[g * 1024 + kk * 2];
                    fma2(acc[0][g], h0, w0.x);
                    fma2(acc[0][g], h1, w0.y);
                    ulonglong2 w1 = *(const ulonglong2*)&Wu1[g * 1024 + kk * 2];
                    fma2(acc[1][g], h0, w1.x);
                    fma2(acc[1][g], h1, w1.y);
                }
            }
        }

        // write partials (lane-contiguous -> conflict-free STS.64)
        #pragma unroll
        for (int un = 0; un < 2; un++)
            #pragma unroll
            for (int g = 0; g < 4; g++)
                *(ull*)&ps[kq][up * 2 + un][g][b0] = acc[un][g];

        // issue xg loads BEFORE the sync so DRAM latency overlaps the barrier wait
        float xv[4];
        if (tid < 256) {
            #pragma unroll
            for (int g = 0; g < 4; g++)
                xv[g] = ldcs32(&g_xg[((size_t)t * G4 + g * 512 + ej) * 64 + eb]);
        }
        __syncthreads();

        // ---- epilogue: 256 threads, one per (unit, batch) ----
        if (tid < 256) {
            float s[4];
            #pragma unroll
            for (int g = 0; g < 4; g++) {
                float a = xv[g];
                #pragma unroll
                for (int q = 0; q < 8; q++) a += ps[q][eu][g][eb];  // conflict-free LDS.32
                s[g] = a;
            }
            float i_ = sigm(s[0]);
            float f_ = sigm(s[1]);
            float gg = tanh_fast(s[2]);
            float o_ = sigm(s[3]);
            cc = f_ * cc + i_ * gg;
            float hh = o_ * tanh_fast(cc);

            g_h[(t + 1) & 1][ej * 64 + eb] = hh;    // tid-linear -> coalesced
            if (layer == 0) hs[eb][eu] = hh;        // 5-padded -> conflict-free
        }

        if (layer == 0) {
            __syncthreads();
            if (tid < 64) {
                float4 v = make_float4(hs[tid][0], hs[tid][1], hs[tid][2], hs[tid][3]);
                *(float4*)&g_hseq[((size_t)t * 64 + tid) * 512 + blockIdx.x * 4] = v;
            }
        }

        // ---- grid barrier (skip after last step) ----
        if (t != S - 1) {
            __syncthreads();
            if (tid == 0) {
                unsigned gen = g_bar_gen;
                __threadfence();   // drain h stores to L2
                if (atomicAdd(&g_bar_cnt, 1u) == NCTA - 1) {
                    g_bar_cnt = 0;
                    __threadfence();
                    g_bar_gen = gen + 1;
                } else {
                    while (g_bar_gen == gen) { }
                }
                __threadfence();   // gpu-scope fence -> CCTL.IVALL: L1 coherence for h
            }
            __syncthreads();
        }
    }
}

// ---------------- final FC: out[b][o] = h_last[:,b] . W_fc[o][:] + b_fc[o] ----------------
__global__ void fc_kernel(const float* __restrict__ Wfc, const float* __restrict__ bfc,
                          float* __restrict__ out)
{
    __shared__ float hcol[H];
    int b = blockIdx.x;
    int o = threadIdx.x;   // 64 threads
    for (int k = o; k < H; k += 64) hcol[k] = g_h[0][k * 64 + b];
    __syncthreads();
    float acc = __ldg(&bfc[o]);
    #pragma unroll 8
    for (int k = 0; k < H; k++) acc += hcol[k] * __ldg(&Wfc[o * 512 + k]);
    out[b * 64 + o] = acc;
}

// ---------------- launch ----------------
extern "C" void kernel_launch(void* const* d_in, const int* in_sizes, int n_in,
                              void* d_out, int out_size)
{
    const float* x      = (const float*)d_in[0];
    const float* W_ih_0 = (const float*)d_in[1];
    const float* W_hh_0 = (const float*)d_in[2];
    const float* b_ih_0 = (const float*)d_in[3];
    const float* b_hh_0 = (const float*)d_in[4];
    const float* W_ih_1 = (const float*)d_in[5];
    const float* W_hh_1 = (const float*)d_in[6];
    const float* b_ih_1 = (const float*)d_in[7];
    const float* b_hh_1 = (const float*)d_in[8];
    const float* W_fc   = (const float*)d_in[9];
    const float* b_fc   = (const float*)d_in[10];
    float* out = (float*)d_out;

    cudaFuncSetAttribute(lstm_persist_kernel, cudaFuncAttributeMaxDynamicSharedMemorySize, 65536);

    prep_wdup_kernel<<<8192, 256>>>(W_hh_0, W_hh_1);

    // ---- layer 0 ----
    gemm_bias_kernel<<<dim3(16, 128), 256>>>(x, W_ih_0, b_ih_0, b_hh_0, INSZ, 0);
    lstm_persist_kernel<<<NCTA, 512, 65536>>>(0);

    // ---- layer 1 ----
    gemm_bias_kernel<<<dim3(16, 128), 256>>>(x, W_ih_1, b_ih_1, b_hh_1, H, 1);
    lstm_persist_kernel<<<NCTA, 512, 65536>>>(1);

    // ---- head ----
    fc_kernel<<<64, 64>>>(W_fc, b_fc, out);
}